// round 8
// baseline (speedup 1.0000x reference)
#include <cuda_runtime.h>
#include <cuda_fp16.h>
#include <mma.h>
#include <cstdint>

// UpConvBlock: y = ConvTranspose2d(x, w1, k=4, s=2, p=1) + b1
//              out = PAC-3x3(y, guide, w2) + b2
// R8: fp16 HMMA with split weights (A = Ah + Al), B built from a smem-resident
// fp32 halo loaded once per K-chunk (kills per-stage global loads + index math).

#define H1 64
#define W1 64
#define CIN 256
#define CMID 128
#define H2 128
#define W2 128
#define BATCH 4

typedef unsigned long long u64;
typedef unsigned int u32;

using namespace nvcuda;

__device__ __forceinline__ u32 pack_f16x2(float lo, float hi) {
    u32 r; asm("cvt.rn.f16x2.f32 %0, %1, %2;" : "=r"(r) : "f"(hi), "f"(lo)); return r;
}
__device__ __forceinline__ u32 smem_u32(const void* p) {
    u32 a; asm("{ .reg .u64 t; cvta.to.shared.u64 t, %1; cvt.u32.u64 %0, t; }" : "=r"(a) : "l"(p));
    return a;
}
__device__ __forceinline__ void cpasync16(u32 dst, const void* src) {
    asm volatile("cp.async.ca.shared.global [%0], [%1], 16;" :: "r"(dst), "l"(src));
}
__device__ __forceinline__ void cpasync_wait() {
    asm volatile("cp.async.commit_group;\n\tcp.async.wait_group 0;" ::: "memory");
}

// ---------------- scratch globals ----------------
__device__ float g_y[BATCH * CMID * H2 * W2];
__device__ __align__(128) __half g_w1h[4 * 16 * 128 * 64];   // [par][kc][o][krow]
__device__ __align__(128) __half g_w1l[4 * 16 * 128 * 64];
__device__ __align__(128) __half g_w2h[9 * 2 * 128 * 64];    // [ij][kc][o][c]
__device__ __align__(128) __half g_w2l[9 * 2 * 128 * 64];

// smem layout (shared by both kernels): A stride 72 halves, B stride 72 halves
#define SA 72
#define SB 72
#define OFF_AH 0
#define OFF_AL 18432
#define OFF_B  36864
#define OFF_HALO 46080
// convt halo: 16c x 9 x 12 fp32 = 6912 B
#define CONVT_SMEM (46080 + 6912)            // 52992
// pac halo: 64c x 10 x 12 fp32 = 30720 B ; ks after
#define P_KS (46080 + 30720)                 // 76800
#define PAC_SMEM (P_KS + 9 * 64 * 4)         // 79104

// ---------------------------------------------------------------------------
// Weight pre-split kernels (fp16 hi/lo)
// ---------------------------------------------------------------------------
__global__ void split_w1(const float* __restrict__ w1) {
    int idx = blockIdx.x * 256 + threadIdx.x;        // 524288
    if (idx >= 4 * 16 * 128 * 64) return;
    int kr = idx & 63;
    int o  = (idx >> 6) & 127;
    int kc = (idx >> 13) & 15;
    int par = idx >> 17;
    int di = par >> 1, dj = par & 1;
    int c = kc * 16 + (kr >> 2);
    int tap = kr & 3;
    int t = tap >> 1, u = tap & 1;
    float v = w1[(c * CMID + o) * 16 + (3 - di - 2 * t) * 4 + (3 - dj - 2 * u)];
    __half h = __float2half_rn(v);
    g_w1h[idx] = h;
    g_w1l[idx] = __float2half_rn(v - __half2float(h));
}

__global__ void split_w2(const float* __restrict__ w2) {
    int idx = blockIdx.x * 256 + threadIdx.x;        // 147456
    if (idx >= 9 * 2 * 128 * 64) return;
    int ck = idx & 63;
    int o  = (idx >> 6) & 127;
    int kc = (idx >> 13) & 1;
    int ij = idx >> 14;
    int i = ij / 3, j = ij % 3;
    int c = kc * 64 + ck;
    float v = w2[(c * CMID + o) * 9 + (2 - i) * 3 + (2 - j)];
    __half h = __float2half_rn(v);
    g_w2h[idx] = h;
    g_w2l[idx] = __float2half_rn(v - __half2float(h));
}

// ---------------------------------------------------------------------------
// Shared MMA stage: A[128][64] hi+lo, B[64][64], 2 products per k-step.
// ---------------------------------------------------------------------------
template<typename AccT>
__device__ __forceinline__ void mma_stage(const char* smem, int mo, int np, AccT (&acc)[2][2]) {
#pragma unroll
    for (int k0 = 0; k0 < 4; k0++) {
        wmma::fragment<wmma::matrix_b, 16, 16, 16, __half, wmma::row_major> bf[2];
        const __half* B = (const __half*)(smem + OFF_B);
        wmma::load_matrix_sync(bf[0], B + (k0 * 16) * SB + np, SB);
        wmma::load_matrix_sync(bf[1], B + (k0 * 16) * SB + np + 16, SB);
#pragma unroll
        for (int s = 0; s < 2; s++) {
            const __half* A = (const __half*)(smem + (s ? OFF_AL : OFF_AH));
            wmma::fragment<wmma::matrix_a, 16, 16, 16, __half, wmma::row_major> af[2];
            wmma::load_matrix_sync(af[0], A + mo * SA + k0 * 16, SA);
            wmma::load_matrix_sync(af[1], A + (mo + 16) * SA + k0 * 16, SA);
#pragma unroll
            for (int m = 0; m < 2; m++)
#pragma unroll
                for (int n = 0; n < 2; n++)
                    wmma::mma_sync(acc[m][n], af[m], bf[n], acc[m][n]);
        }
    }
}

// ---------------------------------------------------------------------------
// Kernel 1: conv_transpose via parity decomposition. Block: 128o x 64px.
// K = 1024 in 16 chunks of 64 (16c x 4taps); x halo smem-staged per chunk.
// ---------------------------------------------------------------------------
__global__ __launch_bounds__(256, 3) void convt_wmma(const float* __restrict__ x,
                                                     const float* __restrict__ b1) {
    extern __shared__ __align__(128) char smem[];
    const u32 sb = smem_u32(smem);
    const int tid = threadIdx.x;
    const int wid = tid >> 5;
    const int mo = (wid & 3) * 32;
    const int np = (wid >> 2) * 32;

    const int bz = blockIdx.z;
    const int b  = bz >> 2;
    const int par = bz & 3;
    const int di = par >> 1, dj = par & 1;
    const int i0 = blockIdx.y * 8;
    const int j0 = blockIdx.x * 8;
    const int ihBase = i0 + (di == 0 ? -1 : 0);
    const int jwBase = j0 + (dj == 0 ? -1 : 0);

    wmma::fragment<wmma::accumulator, 16, 16, 16, float> acc[2][2];
#pragma unroll
    for (int m = 0; m < 2; m++)
#pragma unroll
        for (int n = 0; n < 2; n++) wmma::fill_fragment(acc[m][n], 0.f);

    const float* xb = x + b * (CIN * H1 * W1);
    float* halo = (float*)(smem + OFF_HALO);        // [16][9][12]

    for (int kc = 0; kc < 16; kc++) {
        const int c0 = kc * 16;
        // halo load (region disjoint from A/B read by in-flight MMA)
        for (int idx = tid; idx < 1440; idx += 256) {
            int c = idx / 90;
            int rem = idx - c * 90;
            int r = rem / 10;
            int col = rem - r * 10;
            int gi = ihBase + r, gj = jwBase + col;
            float v = 0.f;
            if ((unsigned)gi < (unsigned)H1 && (unsigned)gj < (unsigned)W1)
                v = xb[(c0 + c) * (H1 * W1) + gi * W1 + gj];
            halo[c * 108 + r * 12 + col] = v;
        }
        __syncthreads();   // halo visible + prev MMA done before A/B overwrite

        // A: cp.async pre-split fp16 weights
        {
            const __half* wAh = g_w1h + (par * 16 + kc) * 8192;
            const __half* wAl = g_w1l + (par * 16 + kc) * 8192;
#pragma unroll
            for (int q = 0; q < 4; q++) {
                int p = tid + q * 256;
                int o = p >> 3, ch = p & 7;
                u32 dsto = (u32)(o * (SA * 2) + ch * 16);
                cpasync16(sb + OFF_AH + dsto, wAh + o * 64 + ch * 8);
                cpasync16(sb + OFF_AL + dsto, wAl + o * 64 + ch * 8);
            }
        }
        // B from smem halo: krow = c_local*4 + t*2 + u
#pragma unroll
        for (int q = 0; q < 8; q++) {
            int p = tid + q * 256;
            int krow = p >> 5;
            int px0 = (p & 31) * 2;
            int cl = krow >> 2, t = (krow >> 1) & 1, u = krow & 1;
            int r = px0 >> 3, cw = px0 & 7;
            const float* hp = halo + cl * 108 + (r + t) * 12 + (cw + u);
            *(u32*)(smem + OFF_B + krow * (SB * 2) + px0 * 2) = pack_f16x2(hp[0], hp[1]);
        }
        cpasync_wait();
        __syncthreads();

        mma_stage(smem, mo, np, acc);
    }

    // epilogue: fbuf [128][72] fp32 (overlays A), parity scatter into g_y
    __syncthreads();
    float* fbuf = (float*)smem;
#pragma unroll
    for (int m = 0; m < 2; m++)
#pragma unroll
        for (int n = 0; n < 2; n++)
            wmma::store_matrix_sync(fbuf + (mo + m * 16) * SB + np + n * 16,
                                    acc[m][n], SB, wmma::mem_row_major);
    __syncthreads();
    for (int idx = tid; idx < 8192; idx += 256) {
        int o = idx >> 6;
        int n = idx & 63;
        int r = n >> 3, cw = n & 7;
        float v = fbuf[o * SB + n] + __ldg(&b1[o]);
        g_y[((b * CMID + o) * H2 + 2 * (i0 + r) + di) * W2 + 2 * (j0 + cw) + dj] = v;
    }
}

// ---------------------------------------------------------------------------
// Kernel 2: PAC 3x3. Block: 128o x 64px. 2 kc chunks; y halo smem-staged once
// per chunk, reused by all 9 ij stages.
// ---------------------------------------------------------------------------
__global__ __launch_bounds__(256, 2) void pac_wmma(const float* __restrict__ guide,
                                                   const float* __restrict__ b2,
                                                   float* __restrict__ out) {
    extern __shared__ __align__(128) char smem[];
    const u32 sb = smem_u32(smem);
    const int tid = threadIdx.x;
    const int wid = tid >> 5;
    const int mo = (wid & 3) * 32;
    const int np = (wid >> 2) * 32;

    const int b  = blockIdx.z;
    const int h0 = blockIdx.y * 8;
    const int w0 = blockIdx.x * 8;

    float* ks = (float*)(smem + P_KS);      // [9][64]
    float* gs = (float*)smem;               // overlay: [32][10][12]
    float* halo = (float*)(smem + OFF_HALO);// [64][10][12]

    // ---- Phase A: guide kernel ----
    for (int t = tid; t < 576; t += 256) ks[t] = 0.f;

    for (int cc = 0; cc < CMID; cc += 32) {
        __syncthreads();
        for (int idx = tid; idx < 3200; idx += 256) {
            int c = idx / 100;
            int r = (idx % 100) / 10;
            int col = idx % 10;
            int gh = h0 - 1 + r, gw = w0 - 1 + col;
            float v = 0.f;
            if ((unsigned)gh < (unsigned)H2 && (unsigned)gw < (unsigned)W2)
                v = guide[((b * CMID + cc + c) * H2 + gh) * W2 + gw];
            gs[c * 120 + r * 12 + col] = v;
        }
        __syncthreads();
        for (int idx = tid; idx < 576; idx += 256) {
            int ij = idx >> 6;
            int p  = idx & 63;
            int i = ij / 3, j = ij % 3;
            int r = p >> 3, cw = p & 7;
            float s = 0.f;
#pragma unroll
            for (int c = 0; c < 32; c++) {
                float d = gs[c * 120 + (r + i) * 12 + (cw + j)] - gs[c * 120 + (r + 1) * 12 + (cw + 1)];
                s += d * d;
            }
            ks[idx] += s;
        }
    }
    __syncthreads();
    for (int t = tid; t < 576; t += 256) ks[t] = __expf(-0.5f * ks[t]);
    __syncthreads();

    // ---- Phase B ----
    wmma::fragment<wmma::accumulator, 16, 16, 16, float> acc[2][2];
#pragma unroll
    for (int m = 0; m < 2; m++)
#pragma unroll
        for (int n = 0; n < 2; n++) wmma::fill_fragment(acc[m][n], 0.f);

    const float* yb = g_y + b * (CMID * H2 * W2);

    for (int kc = 0; kc < 2; kc++) {
        const int c0 = kc * 64;
        // halo load: 64c x 10 x 10 (zero-padded), reused by all 9 ij
        for (int idx = tid; idx < 6400; idx += 256) {
            int c = idx / 100;
            int rem = idx - c * 100;
            int r = rem / 10;
            int col = rem - r * 10;
            int gh = h0 - 1 + r, gw = w0 - 1 + col;
            float v = 0.f;
            if ((unsigned)gh < (unsigned)H2 && (unsigned)gw < (unsigned)W2)
                v = yb[(c0 + c) * (H2 * W2) + gh * W2 + gw];
            halo[c * 120 + r * 12 + col] = v;
        }
        for (int ij = 0; ij < 9; ij++) {
            const int i = ij / 3, j = ij % 3;
            __syncthreads();   // halo visible; prev MMA done before A/B overwrite
            // A: cp.async pre-split fp16 weights
            {
                const __half* wAh = g_w2h + (ij * 2 + kc) * 8192;
                const __half* wAl = g_w2l + (ij * 2 + kc) * 8192;
#pragma unroll
                for (int q = 0; q < 4; q++) {
                    int p = tid + q * 256;
                    int o = p >> 3, ch = p & 7;
                    u32 dsto = (u32)(o * (SA * 2) + ch * 16);
                    cpasync16(sb + OFF_AH + dsto, wAh + o * 64 + ch * 8);
                    cpasync16(sb + OFF_AL + dsto, wAl + o * 64 + ch * 8);
                }
            }
            // B = halo * k
#pragma unroll
            for (int q = 0; q < 8; q++) {
                int p = tid + q * 256;
                int cl = p >> 5;
                int px0 = (p & 31) * 2;
                int r = px0 >> 3, cw = px0 & 7;
                const float* hp = halo + cl * 120 + (r + i) * 12 + (cw + j);
                float k0 = ks[ij * 64 + px0];
                float k1 = ks[ij * 64 + px0 + 1];
                *(u32*)(smem + OFF_B + cl * (SB * 2) + px0 * 2) = pack_f16x2(hp[0] * k0, hp[1] * k1);
            }
            cpasync_wait();
            __syncthreads();

            mma_stage(smem, mo, np, acc);
        }
        __syncthreads();   // last MMA of chunk done before halo reload
    }

    // ---- Epilogue ----
    float* fbuf = (float*)smem;              // [128][72]
#pragma unroll
    for (int m = 0; m < 2; m++)
#pragma unroll
        for (int n = 0; n < 2; n++)
            wmma::store_matrix_sync(fbuf + (mo + m * 16) * SB + np + n * 16,
                                    acc[m][n], SB, wmma::mem_row_major);
    __syncthreads();
    for (int idx = tid; idx < 8192; idx += 256) {
        int o = idx >> 6;
        int n = idx & 63;
        float v = fbuf[o * SB + n] + __ldg(&b2[o]);
        out[((b * CMID + o) * H2 + h0 + (n >> 3)) * W2 + w0 + (n & 7)] = v;
    }
}

extern "C" void kernel_launch(void* const* d_in, const int* in_sizes, int n_in,
                              void* d_out, int out_size) {
    const float* x     = (const float*)d_in[0];
    const float* guide = (const float*)d_in[1];
    const float* w1    = (const float*)d_in[2];
    const float* b1    = (const float*)d_in[3];
    const float* w2    = (const float*)d_in[4];
    const float* b2    = (const float*)d_in[5];
    float* out = (float*)d_out;

    cudaFuncSetAttribute(convt_wmma, cudaFuncAttributeMaxDynamicSharedMemorySize, CONVT_SMEM);
    cudaFuncSetAttribute(pac_wmma, cudaFuncAttributeMaxDynamicSharedMemorySize, PAC_SMEM);

    split_w1<<<(4 * 16 * 128 * 64 + 255) / 256, 256>>>(w1);
    split_w2<<<(9 * 2 * 128 * 64 + 255) / 256, 256>>>(w2);
    convt_wmma<<<dim3(8, 8, BATCH * 4), 256, CONVT_SMEM>>>(x, b1);
    pac_wmma<<<dim3(16, 16, BATCH), 256, PAC_SMEM>>>(guide, b2, out);
}

// round 10
// speedup vs baseline: 1.2115x; 1.2115x over previous
#include <cuda_runtime.h>
#include <cuda_fp16.h>
#include <mma.h>
#include <cstdint>

// UpConvBlock: y = ConvTranspose2d(x, w1, k=4, s=2, p=1) + b1
//              out = PAC-3x3(y, guide, w2) + b2
// R10: R9 (single fp16 product, 4 CTAs/SM) with the smem-size fix: the fp32
// epilogue buffer [128][72] = 36864 B must fit in dynamic smem.

#define H1 64
#define W1 64
#define CIN 256
#define CMID 128
#define H2 128
#define W2 128
#define BATCH 4

typedef unsigned long long u64;
typedef unsigned int u32;

using namespace nvcuda;

__device__ __forceinline__ u32 pack_f16x2(float lo, float hi) {
    u32 r; asm("cvt.rn.f16x2.f32 %0, %1, %2;" : "=r"(r) : "f"(hi), "f"(lo)); return r;
}
__device__ __forceinline__ u32 smem_u32(const void* p) {
    u32 a; asm("{ .reg .u64 t; cvta.to.shared.u64 t, %1; cvt.u32.u64 %0, t; }" : "=r"(a) : "l"(p));
    return a;
}
__device__ __forceinline__ void cpasync16(u32 dst, const void* src) {
    asm volatile("cp.async.ca.shared.global [%0], [%1], 16;" :: "r"(dst), "l"(src));
}
__device__ __forceinline__ void cpasync_wait() {
    asm volatile("cp.async.commit_group;\n\tcp.async.wait_group 0;" ::: "memory");
}

// ---------------- scratch globals ----------------
__device__ float g_y[BATCH * CMID * H2 * W2];
__device__ __align__(128) __half g_w1[4 * 16 * 128 * 64];   // [par][kc][o][krow]
__device__ __align__(128) __half g_w2[9 * 2 * 128 * 64];    // [ij][kc][o][c]

// smem layout: A rows (128) stride 72 halves; B rows (64) stride 72 halves.
// Epilogue overlays bytes [0, 36864) as fp32 [128][72] -> smem must cover it.
#define SA 72
#define SB 72
#define OFF_A 0
#define OFF_B 18432
#define FBUF_BYTES 36864                 // 128 * 72 * 4
#define OFF_KS FBUF_BYTES                // pac only: fp32 [9][64]
#define CONVT_SMEM FBUF_BYTES            // 36864
#define PAC_SMEM   (FBUF_BYTES + 2304)   // 39168

// ---------------------------------------------------------------------------
// Weight transpose kernels (fp16)
// ---------------------------------------------------------------------------
__global__ void prep_w1(const float* __restrict__ w1) {
    int idx = blockIdx.x * 256 + threadIdx.x;        // 524288
    if (idx >= 4 * 16 * 128 * 64) return;
    int kr = idx & 63;
    int o  = (idx >> 6) & 127;
    int kc = (idx >> 13) & 15;
    int par = idx >> 17;
    int di = par >> 1, dj = par & 1;
    int c = kc * 16 + (kr >> 2);
    int tap = kr & 3;
    int t = tap >> 1, u = tap & 1;
    g_w1[idx] = __float2half_rn(w1[(c * CMID + o) * 16 + (3 - di - 2 * t) * 4 + (3 - dj - 2 * u)]);
}

__global__ void prep_w2(const float* __restrict__ w2) {
    int idx = blockIdx.x * 256 + threadIdx.x;        // 147456
    if (idx >= 9 * 2 * 128 * 64) return;
    int ck = idx & 63;
    int o  = (idx >> 6) & 127;
    int kc = (idx >> 13) & 1;
    int ij = idx >> 14;
    int i = ij / 3, j = ij % 3;
    int c = kc * 64 + ck;
    g_w2[idx] = __float2half_rn(w2[(c * CMID + o) * 9 + (2 - i) * 3 + (2 - j)]);
}

// ---------------------------------------------------------------------------
// MMA stage: A[128][64], B[64][64], single product per k-step.
// ---------------------------------------------------------------------------
template<typename AccT>
__device__ __forceinline__ void mma_stage(const char* smem, int mo, int np, AccT (&acc)[2][2]) {
#pragma unroll
    for (int k0 = 0; k0 < 4; k0++) {
        const __half* B = (const __half*)(smem + OFF_B);
        const __half* A = (const __half*)(smem + OFF_A);
        wmma::fragment<wmma::matrix_b, 16, 16, 16, __half, wmma::row_major> bf[2];
        wmma::fragment<wmma::matrix_a, 16, 16, 16, __half, wmma::row_major> af[2];
        wmma::load_matrix_sync(bf[0], B + (k0 * 16) * SB + np, SB);
        wmma::load_matrix_sync(bf[1], B + (k0 * 16) * SB + np + 16, SB);
        wmma::load_matrix_sync(af[0], A + mo * SA + k0 * 16, SA);
        wmma::load_matrix_sync(af[1], A + (mo + 16) * SA + k0 * 16, SA);
#pragma unroll
        for (int m = 0; m < 2; m++)
#pragma unroll
            for (int n = 0; n < 2; n++)
                wmma::mma_sync(acc[m][n], af[m], bf[n], acc[m][n]);
    }
}

// ---------------------------------------------------------------------------
// Kernel 1: conv_transpose via parity decomposition. Block: 128o x 64px.
// K = 1024 in 16 chunks of 64 (16c x 4taps each).
// ---------------------------------------------------------------------------
__global__ __launch_bounds__(256, 4) void convt_wmma(const float* __restrict__ x,
                                                     const float* __restrict__ b1) {
    extern __shared__ __align__(128) char smem[];
    const u32 sb = smem_u32(smem);
    const int tid = threadIdx.x;
    const int wid = tid >> 5;
    const int mo = (wid & 3) * 32;
    const int np = (wid >> 2) * 32;

    const int bz = blockIdx.z;
    const int b  = bz >> 2;
    const int par = bz & 3;
    const int di = par >> 1, dj = par & 1;
    const int i0 = blockIdx.y * 8;
    const int j0 = blockIdx.x * 8;
    const int ihBase = i0 + (di == 0 ? -1 : 0);
    const int jwBase = j0 + (dj == 0 ? -1 : 0);

    wmma::fragment<wmma::accumulator, 16, 16, 16, float> acc[2][2];
#pragma unroll
    for (int m = 0; m < 2; m++)
#pragma unroll
        for (int n = 0; n < 2; n++) wmma::fill_fragment(acc[m][n], 0.f);

    const float* xb = x + b * (CIN * H1 * W1);

    for (int kc = 0; kc < 16; kc++) {
        __syncthreads();
        // A: cp.async fp16 weights (row = 64 halves = 128B)
        {
            const __half* wA = g_w1 + (par * 16 + kc) * 8192;
#pragma unroll
            for (int q = 0; q < 4; q++) {
                int p = tid + q * 256;               // 0..1023
                int o = p >> 3, ch = p & 7;
                cpasync16(sb + OFF_A + (u32)(o * (SA * 2) + ch * 16), wA + o * 64 + ch * 8);
            }
        }
        // B: x halo, fp16. krow = c_local*4 + t*2 + u
        const int c0 = kc * 16;
#pragma unroll
        for (int q = 0; q < 8; q++) {
            int p = tid + q * 256;                   // 0..2047 u32 words
            int krow = p >> 5;
            int px0 = (p & 31) * 2;
            int c = c0 + (krow >> 2);
            int t = (krow >> 1) & 1, u = krow & 1;
            int r = px0 >> 3, cw = px0 & 7;
            int h = ihBase + r + t;
            int w = jwBase + cw + u;
            const float* xp = xb + c * (H1 * W1) + h * W1;
            bool okh = (unsigned)h < (unsigned)H1;
            float v0 = (okh && (unsigned)w < (unsigned)W1) ? xp[w] : 0.f;
            float v1 = (okh && (unsigned)(w + 1) < (unsigned)W1) ? xp[w + 1] : 0.f;
            *(u32*)(smem + OFF_B + krow * (SB * 2) + px0 * 2) = pack_f16x2(v0, v1);
        }
        cpasync_wait();
        __syncthreads();

        mma_stage(smem, mo, np, acc);
    }

    // epilogue: fbuf [128][72] fp32 (overlays A+B), parity scatter into g_y
    __syncthreads();
    float* fbuf = (float*)smem;
#pragma unroll
    for (int m = 0; m < 2; m++)
#pragma unroll
        for (int n = 0; n < 2; n++)
            wmma::store_matrix_sync(fbuf + (mo + m * 16) * SB + np + n * 16,
                                    acc[m][n], SB, wmma::mem_row_major);
    __syncthreads();
    for (int idx = tid; idx < 8192; idx += 256) {
        int o = idx >> 6;
        int n = idx & 63;
        int r = n >> 3, cw = n & 7;
        float v = fbuf[o * SB + n] + __ldg(&b1[o]);
        g_y[((b * CMID + o) * H2 + 2 * (i0 + r) + di) * W2 + 2 * (j0 + cw) + dj] = v;
    }
}

// ---------------------------------------------------------------------------
// Kernel 2: PAC 3x3. Block: 128o x 64px (8x8 tile). 2 kc chunks x 9 ij stages.
// ---------------------------------------------------------------------------
__global__ __launch_bounds__(256, 4) void pac_wmma(const float* __restrict__ guide,
                                                   const float* __restrict__ b2,
                                                   float* __restrict__ out) {
    extern __shared__ __align__(128) char smem[];
    const u32 sb = smem_u32(smem);
    const int tid = threadIdx.x;
    const int wid = tid >> 5;
    const int mo = (wid & 3) * 32;
    const int np = (wid >> 2) * 32;

    const int b  = blockIdx.z;
    const int h0 = blockIdx.y * 8;
    const int w0 = blockIdx.x * 8;

    float* ks = (float*)(smem + OFF_KS);    // [9][64]
    float* gs = (float*)smem;               // overlay: [32][10][12]

    // ---- Phase A: guide kernel ----
    for (int t = tid; t < 576; t += 256) ks[t] = 0.f;

    for (int cc = 0; cc < CMID; cc += 32) {
        __syncthreads();
        for (int idx = tid; idx < 3200; idx += 256) {
            int c = idx / 100;
            int r = (idx % 100) / 10;
            int col = idx % 10;
            int gh = h0 - 1 + r, gw = w0 - 1 + col;
            float v = 0.f;
            if ((unsigned)gh < (unsigned)H2 && (unsigned)gw < (unsigned)W2)
                v = guide[((b * CMID + cc + c) * H2 + gh) * W2 + gw];
            gs[c * 120 + r * 12 + col] = v;
        }
        __syncthreads();
        for (int idx = tid; idx < 576; idx += 256) {
            int ij = idx >> 6;
            int p  = idx & 63;
            int i = ij / 3, j = ij % 3;
            int r = p >> 3, cw = p & 7;
            float s = 0.f;
#pragma unroll
            for (int c = 0; c < 32; c++) {
                float d = gs[c * 120 + (r + i) * 12 + (cw + j)] - gs[c * 120 + (r + 1) * 12 + (cw + 1)];
                s += d * d;
            }
            ks[idx] += s;
        }
    }
    __syncthreads();
    for (int t = tid; t < 576; t += 256) ks[t] = __expf(-0.5f * ks[t]);

    // ---- Phase B: 2 kc x 9 ij stages ----
    wmma::fragment<wmma::accumulator, 16, 16, 16, float> acc[2][2];
#pragma unroll
    for (int m = 0; m < 2; m++)
#pragma unroll
        for (int n = 0; n < 2; n++) wmma::fill_fragment(acc[m][n], 0.f);

    const float* yb = g_y + b * (CMID * H2 * W2);

    for (int kc = 0; kc < 2; kc++) {
        for (int ij = 0; ij < 9; ij++) {
            const int i = ij / 3, j = ij % 3;
            __syncthreads();
            // A: cp.async fp16 weights
            {
                const __half* wA = g_w2 + (ij * 2 + kc) * 8192;
#pragma unroll
                for (int q = 0; q < 4; q++) {
                    int p = tid + q * 256;
                    int o = p >> 3, ch = p & 7;
                    cpasync16(sb + OFF_A + (u32)(o * (SA * 2) + ch * 16), wA + o * 64 + ch * 8);
                }
            }
            // B = y * k, fp16
            const int c0 = kc * 64;
#pragma unroll
            for (int q = 0; q < 8; q++) {
                int p = tid + q * 256;               // 0..2047
                int c = c0 + (p >> 5);
                int px0 = (p & 31) * 2;
                int r = px0 >> 3, cw = px0 & 7;
                int h = h0 + r + i - 1;
                int w = w0 + cw + j - 1;
                const float* yp = yb + c * (H2 * W2) + h * W2;
                bool okh = (unsigned)h < (unsigned)H2;
                float v0 = (okh && (unsigned)w < (unsigned)W2) ? yp[w] * ks[ij * 64 + px0] : 0.f;
                float v1 = (okh && (unsigned)(w + 1) < (unsigned)W2) ? yp[w + 1] * ks[ij * 64 + px0 + 1] : 0.f;
                *(u32*)(smem + OFF_B + (p >> 5) * (SB * 2) + px0 * 2) = pack_f16x2(v0, v1);
            }
            cpasync_wait();
            __syncthreads();

            mma_stage(smem, mo, np, acc);
        }
    }

    // ---- Epilogue ----
    __syncthreads();
    float* fbuf = (float*)smem;              // [128][72] = 36864 B, fits PAC_SMEM
#pragma unroll
    for (int m = 0; m < 2; m++)
#pragma unroll
        for (int n = 0; n < 2; n++)
            wmma::store_matrix_sync(fbuf + (mo + m * 16) * SB + np + n * 16,
                                    acc[m][n], SB, wmma::mem_row_major);
    __syncthreads();
    for (int idx = tid; idx < 8192; idx += 256) {
        int o = idx >> 6;
        int n = idx & 63;
        float v = fbuf[o * SB + n] + __ldg(&b2[o]);
        out[((b * CMID + o) * H2 + h0 + (n >> 3)) * W2 + w0 + (n & 7)] = v;
    }
}

extern "C" void kernel_launch(void* const* d_in, const int* in_sizes, int n_in,
                              void* d_out, int out_size) {
    const float* x     = (const float*)d_in[0];
    const float* guide = (const float*)d_in[1];
    const float* w1    = (const float*)d_in[2];
    const float* b1    = (const float*)d_in[3];
    const float* w2    = (const float*)d_in[4];
    const float* b2    = (const float*)d_in[5];
    float* out = (float*)d_out;

    cudaFuncSetAttribute(convt_wmma, cudaFuncAttributeMaxDynamicSharedMemorySize, CONVT_SMEM);
    cudaFuncSetAttribute(pac_wmma, cudaFuncAttributeMaxDynamicSharedMemorySize, PAC_SMEM);

    prep_w1<<<(4 * 16 * 128 * 64 + 255) / 256, 256>>>(w1);
    prep_w2<<<(9 * 2 * 128 * 64 + 255) / 256, 256>>>(w2);
    convt_wmma<<<dim3(8, 8, BATCH * 4), 256, CONVT_SMEM>>>(x, b1);
    pac_wmma<<<dim3(16, 16, BATCH), 256, PAC_SMEM>>>(guide, b2, out);
}

// round 12
// speedup vs baseline: 1.4697x; 1.2131x over previous
#include <cuda_runtime.h>
#include <cuda_fp16.h>
#include <mma.h>
#include <cstdint>

// UpConvBlock: y = ConvTranspose2d(x, w1, k=4, s=2, p=1) + b1
//              out = PAC-3x3(y, guide, w2) + b2
// R12: R11 (padded x/y scratch, predicate-free linearized staging, K=128
// chunks, 4 CTAs/SM) with the address-space fix: B staging writes go through
// generic pointers into smem[], not the cvta.to.shared u32 offset.

#define H1 64
#define W1 64
#define CIN 256
#define CMID 128
#define H2 128
#define W2 128
#define BATCH 4

// padded scratch dims
#define XP_H 66
#define XP_W 68
#define XP_CH (XP_H * XP_W)          // 4488
#define YP_H 130
#define YP_W 132
#define YP_CH (YP_H * YP_W)          // 17160

typedef unsigned long long u64;
typedef unsigned int u32;

using namespace nvcuda;

__device__ __forceinline__ u32 pack_f16x2(float lo, float hi) {
    u32 r; asm("cvt.rn.f16x2.f32 %0, %1, %2;" : "=r"(r) : "f"(hi), "f"(lo)); return r;
}
__device__ __forceinline__ u32 smem_u32(const void* p) {
    u32 a; asm("{ .reg .u64 t; cvta.to.shared.u64 t, %1; cvt.u32.u64 %0, t; }" : "=r"(a) : "l"(p));
    return a;
}
__device__ __forceinline__ void cpasync16(u32 dst, const void* src) {
    asm volatile("cp.async.ca.shared.global [%0], [%1], 16;" :: "r"(dst), "l"(src));
}
__device__ __forceinline__ void cpasync_wait() {
    asm volatile("cp.async.commit_group;\n\tcp.async.wait_group 0;" ::: "memory");
}

// ---------------- scratch globals ----------------
__device__ float g_xp[BATCH * CIN * XP_CH];                  // padded x
__device__ float g_yp[BATCH * CMID * YP_CH];                 // padded y
__device__ __align__(128) __half g_w1[4 * 8 * 128 * 128];    // [par][kc][o][krow]
__device__ __align__(128) __half g_w2[9 * 128 * 128];        // [ij][o][c]

// smem: A [128][136] halves, B [128][72] halves
#define SA2 136
#define SB 72
#define OFF_A 0
#define OFF_B 34816
#define OFF_KS 53248                     // pac: fp32 [9][64]
#define CONVT_SMEM 53248
#define PAC_SMEM   55552

// ---------------------------------------------------------------------------
// Prep kernels
// ---------------------------------------------------------------------------
__global__ void prep_w1(const float* __restrict__ w1) {
    int idx = blockIdx.x * 256 + threadIdx.x;        // 524288
    if (idx >= 4 * 8 * 128 * 128) return;
    int kr = idx & 127;
    int o  = (idx >> 7) & 127;
    int kc = (idx >> 14) & 7;
    int par = idx >> 17;
    int di = par >> 1, dj = par & 1;
    int c = kc * 32 + (kr >> 2);
    int tap = kr & 3;
    int t = tap >> 1, u = tap & 1;
    g_w1[idx] = __float2half_rn(w1[(c * CMID + o) * 16 + (3 - di - 2 * t) * 4 + (3 - dj - 2 * u)]);
}

__global__ void prep_w2(const float* __restrict__ w2) {
    int idx = blockIdx.x * 256 + threadIdx.x;        // 147456
    if (idx >= 9 * 128 * 128) return;
    int c  = idx & 127;
    int o  = (idx >> 7) & 127;
    int ij = idx >> 14;
    int i = ij / 3, j = ij % 3;
    g_w2[idx] = __float2half_rn(w2[(c * CMID + o) * 9 + (2 - i) * 3 + (2 - j)]);
}

__global__ void pad_x(const float* __restrict__ x) {
    int idx = blockIdx.x * 256 + threadIdx.x;        // 4595712
    if (idx >= BATCH * CIN * XP_CH) return;
    int col = idx % XP_W;
    int r   = (idx / XP_W) % XP_H;
    int bc  = idx / XP_CH;
    int h = r - 1, w = col - 1;
    float v = 0.f;
    if ((unsigned)h < (unsigned)H1 && (unsigned)w < (unsigned)W1)
        v = x[bc * (H1 * W1) + h * W1 + w];
    g_xp[idx] = v;
}

__global__ void pad_y_border() {
    int idx = blockIdx.x * 256 + threadIdx.x;        // 512 * 776
    if (idx >= BATCH * CMID * 776) return;
    int e  = idx % 776;
    int bo = idx / 776;
    float* base = g_yp + (u64)bo * YP_CH;
    if (e < 132) base[e] = 0.f;                              // row 0
    else if (e < 264) base[129 * 132 + (e - 132)] = 0.f;     // row 129
    else {
        int t = e - 264;
        int r = 1 + (t >> 2);
        int c = t & 3;
        int col = (c == 0) ? 0 : (128 + c);                  // 0,129,130,131
        base[r * 132 + col] = 0.f;
    }
}

// ---------------------------------------------------------------------------
// MMA stage: A[128][128], B[128][64], 8 k-steps.
// ---------------------------------------------------------------------------
template<typename AccT>
__device__ __forceinline__ void mma_stage(const char* smem, int mo, int np, AccT (&acc)[2][2]) {
#pragma unroll
    for (int k0 = 0; k0 < 8; k0++) {
        const __half* B = (const __half*)(smem + OFF_B);
        const __half* A = (const __half*)(smem + OFF_A);
        wmma::fragment<wmma::matrix_b, 16, 16, 16, __half, wmma::row_major> bf[2];
        wmma::fragment<wmma::matrix_a, 16, 16, 16, __half, wmma::row_major> af[2];
        wmma::load_matrix_sync(bf[0], B + (k0 * 16) * SB + np, SB);
        wmma::load_matrix_sync(bf[1], B + (k0 * 16) * SB + np + 16, SB);
        wmma::load_matrix_sync(af[0], A + mo * SA2 + k0 * 16, SA2);
        wmma::load_matrix_sync(af[1], A + (mo + 16) * SA2 + k0 * 16, SA2);
#pragma unroll
        for (int m = 0; m < 2; m++)
#pragma unroll
            for (int n = 0; n < 2; n++)
                wmma::mma_sync(acc[m][n], af[m], bf[n], acc[m][n]);
    }
}

// ---------------------------------------------------------------------------
// Kernel 1: conv_transpose (parity decomposition). Block: 128o x 64px.
// K = 1024 in 8 chunks of 128 (32c x 4taps).
// ---------------------------------------------------------------------------
__global__ __launch_bounds__(256, 4) void convt_wmma(const float* __restrict__ b1) {
    extern __shared__ __align__(128) char smem[];
    const u32 sb = smem_u32(smem);
    const int tid = threadIdx.x;
    const int wid = tid >> 5;
    const int mo = (wid & 3) * 32;
    const int np = (wid >> 2) * 32;

    const int bz = blockIdx.z;
    const int b  = bz >> 2;
    const int par = bz & 3;
    const int di = par >> 1, dj = par & 1;
    const int i0 = blockIdx.y * 8;
    const int j0 = blockIdx.x * 8;

    // per-thread staging coords (q-invariant)
    const int px0 = (tid & 31) * 2;
    const int r = px0 >> 3, cw = px0 & 7;
    const int tap = wid & 3;
    const int t = tap >> 1, u = tap & 1;

    // padded x base: c = kc*32 + (wid>>2) + 2q ; krow = wid + 8q
    const float* xbase = g_xp + ((u64)(b * CIN + (wid >> 2)) * XP_CH)
                       + (i0 + di + r + t) * XP_W + (j0 + dj + cw + u);
    char* bsm = smem + OFF_B + wid * (SB * 2) + px0 * 2;    // generic ptr (FIX)

    wmma::fragment<wmma::accumulator, 16, 16, 16, float> acc[2][2];
#pragma unroll
    for (int m = 0; m < 2; m++)
#pragma unroll
        for (int n = 0; n < 2; n++) wmma::fill_fragment(acc[m][n], 0.f);

    for (int kc = 0; kc < 8; kc++) {
        __syncthreads();
        // A: cp.async weights, 128 rows x 256B
        {
            const __half* wA = g_w1 + (par * 8 + kc) * 16384;
#pragma unroll
            for (int q = 0; q < 8; q++) {
                int p = tid + q * 256;               // 0..2047 float4
                int o = p >> 4, ch = p & 15;
                cpasync16(sb + OFF_A + (u32)(o * (SA2 * 2) + ch * 16), wA + o * 128 + ch * 8);
            }
        }
        // B: padded x, no predicates, linear addresses
        const float* xs = xbase + kc * (32 * XP_CH);
#pragma unroll
        for (int q = 0; q < 16; q++) {
            float v0 = xs[0], v1 = xs[1];
            *(u32*)(bsm + q * (8 * SB * 2)) = pack_f16x2(v0, v1);
            xs += 2 * XP_CH;
        }
        cpasync_wait();
        __syncthreads();

        mma_stage(smem, mo, np, acc);
    }

    // epilogue: fbuf [128][72] fp32, parity scatter into padded g_yp
    __syncthreads();
    float* fbuf = (float*)smem;
#pragma unroll
    for (int m = 0; m < 2; m++)
#pragma unroll
        for (int n = 0; n < 2; n++)
            wmma::store_matrix_sync(fbuf + (mo + m * 16) * SB + np + n * 16,
                                    acc[m][n], SB, wmma::mem_row_major);
    __syncthreads();
    for (int idx = tid; idx < 8192; idx += 256) {
        int o = idx >> 6;
        int n = idx & 63;
        int rr = n >> 3, cc = n & 7;
        float v = fbuf[o * SB + n] + __ldg(&b1[o]);
        g_yp[(u64)(b * CMID + o) * YP_CH + (2 * (i0 + rr) + di + 1) * YP_W + 2 * (j0 + cc) + dj + 1] = v;
    }
}

// ---------------------------------------------------------------------------
// Kernel 2: PAC 3x3. Block: 128o x 64px (8x8 tile). 9 ij stages, K=128 each.
// ---------------------------------------------------------------------------
__global__ __launch_bounds__(256, 4) void pac_wmma(const float* __restrict__ guide,
                                                   const float* __restrict__ b2,
                                                   float* __restrict__ out) {
    extern __shared__ __align__(128) char smem[];
    const u32 sb = smem_u32(smem);
    const int tid = threadIdx.x;
    const int wid = tid >> 5;
    const int mo = (wid & 3) * 32;
    const int np = (wid >> 2) * 32;

    const int b  = blockIdx.z;
    const int h0 = blockIdx.y * 8;
    const int w0 = blockIdx.x * 8;

    float* ks = (float*)(smem + OFF_KS);    // [9][64]
    float* gs = (float*)smem;               // overlay: [32][10][12]

    // ---- Phase A: guide kernel ----
    for (int tt = tid; tt < 576; tt += 256) ks[tt] = 0.f;

    for (int cc = 0; cc < CMID; cc += 32) {
        __syncthreads();
        for (int idx = tid; idx < 3200; idx += 256) {
            int c = idx / 100;
            int rr = (idx % 100) / 10;
            int col = idx % 10;
            int gh = h0 - 1 + rr, gw = w0 - 1 + col;
            float v = 0.f;
            if ((unsigned)gh < (unsigned)H2 && (unsigned)gw < (unsigned)W2)
                v = guide[((b * CMID + cc + c) * H2 + gh) * W2 + gw];
            gs[c * 120 + rr * 12 + col] = v;
        }
        __syncthreads();
        for (int idx = tid; idx < 576; idx += 256) {
            int ij = idx >> 6;
            int p  = idx & 63;
            int i = ij / 3, j = ij % 3;
            int rr = p >> 3, cww = p & 7;
            float s = 0.f;
#pragma unroll
            for (int c = 0; c < 32; c++) {
                float d = gs[c * 120 + (rr + i) * 12 + (cww + j)] - gs[c * 120 + (rr + 1) * 12 + (cww + 1)];
                s += d * d;
            }
            ks[idx] += s;
        }
    }
    __syncthreads();
    for (int tt = tid; tt < 576; tt += 256) ks[tt] = __expf(-0.5f * ks[tt]);
    __syncthreads();

    // ---- Phase B: 9 ij stages ----
    const int px0 = (tid & 31) * 2;
    const int r = px0 >> 3, cw = px0 & 7;
    // padded y base: c = wid + 8q; tap (0,0) reads padded (h0+r, w0+cw)
    const float* ybase = g_yp + ((u64)(b * CMID + wid) * YP_CH)
                       + (h0 + r) * YP_W + (w0 + cw);
    char* bsm = smem + OFF_B + wid * (SB * 2) + px0 * 2;    // generic ptr (FIX)

    wmma::fragment<wmma::accumulator, 16, 16, 16, float> acc[2][2];
#pragma unroll
    for (int m = 0; m < 2; m++)
#pragma unroll
        for (int n = 0; n < 2; n++) wmma::fill_fragment(acc[m][n], 0.f);

    for (int ij = 0; ij < 9; ij++) {
        const int i = ij / 3, j = ij % 3;
        __syncthreads();
        // A: cp.async weights
        {
            const __half* wA = g_w2 + ij * 16384;
#pragma unroll
            for (int q = 0; q < 8; q++) {
                int p = tid + q * 256;
                int o = p >> 4, ch = p & 15;
                cpasync16(sb + OFF_A + (u32)(o * (SA2 * 2) + ch * 16), wA + o * 128 + ch * 8);
            }
        }
        // B = y * k (padded y, no predicates)
        const float k0v = ks[ij * 64 + px0];
        const float k1v = ks[ij * 64 + px0 + 1];
        const float* ys = ybase + i * YP_W + j;
#pragma unroll
        for (int q = 0; q < 16; q++) {
            float v0 = ys[0] * k0v, v1 = ys[1] * k1v;
            *(u32*)(bsm + q * (8 * SB * 2)) = pack_f16x2(v0, v1);
            ys += 8 * YP_CH;
        }
        cpasync_wait();
        __syncthreads();

        mma_stage(smem, mo, np, acc);
    }

    // ---- Epilogue ----
    __syncthreads();
    float* fbuf = (float*)smem;              // [128][72]
#pragma unroll
    for (int m = 0; m < 2; m++)
#pragma unroll
        for (int n = 0; n < 2; n++)
            wmma::store_matrix_sync(fbuf + (mo + m * 16) * SB + np + n * 16,
                                    acc[m][n], SB, wmma::mem_row_major);
    __syncthreads();
    for (int idx = tid; idx < 8192; idx += 256) {
        int o = idx >> 6;
        int n = idx & 63;
        float v = fbuf[o * SB + n] + __ldg(&b2[o]);
        out[((b * CMID + o) * H2 + h0 + (n >> 3)) * W2 + w0 + (n & 7)] = v;
    }
}

extern "C" void kernel_launch(void* const* d_in, const int* in_sizes, int n_in,
                              void* d_out, int out_size) {
    const float* x     = (const float*)d_in[0];
    const float* guide = (const float*)d_in[1];
    const float* w1    = (const float*)d_in[2];
    const float* b1    = (const float*)d_in[3];
    const float* w2    = (const float*)d_in[4];
    const float* b2    = (const float*)d_in[5];
    float* out = (float*)d_out;

    cudaFuncSetAttribute(convt_wmma, cudaFuncAttributeMaxDynamicSharedMemorySize, CONVT_SMEM);
    cudaFuncSetAttribute(pac_wmma, cudaFuncAttributeMaxDynamicSharedMemorySize, PAC_SMEM);

    prep_w1<<<(4 * 8 * 128 * 128 + 255) / 256, 256>>>(w1);
    prep_w2<<<(9 * 128 * 128 + 255) / 256, 256>>>(w2);
    pad_x<<<(BATCH * CIN * XP_CH + 255) / 256, 256>>>(x);
    pad_y_border<<<(BATCH * CMID * 776 + 255) / 256, 256>>>();
    convt_wmma<<<dim3(8, 8, BATCH * 4), 256, CONVT_SMEM>>>(b1);
    pac_wmma<<<dim3(16, 16, BATCH), 256, PAC_SMEM>>>(guide, b2, out);
}

// round 13
// speedup vs baseline: 1.5737x; 1.0708x over previous
#include <cuda_runtime.h>
#include <cuda_fp16.h>
#include <mma.h>
#include <cstdint>

// UpConvBlock: y = ConvTranspose2d(x, w1, k=4, s=2, p=1) + b1
//              out = PAC-3x3(y, guide, w2) + b2
// R13: R12 + shifted fp16 copies of padded x and y (B[i] = A[i+1]) so every
// tap shift becomes an ALIGNED u32 fp16 load. convt staging = LDG.32+STS;
// pac staging = LDG.32+HMUL2+STS with k pre-packed half2. 4 CTAs/SM.

#define H1 64
#define W1 64
#define CIN 256
#define CMID 128
#define H2 128
#define W2 128
#define BATCH 4

// padded scratch dims
#define XP_H 66
#define XP_W 68
#define XP_CH (XP_H * XP_W)          // 4488 (even)
#define YP_H 130
#define YP_W 132
#define YP_CH (YP_H * YP_W)          // 17160 (even)

typedef unsigned long long u64;
typedef unsigned int u32;

using namespace nvcuda;

__device__ __forceinline__ u32 smem_u32(const void* p) {
    u32 a; asm("{ .reg .u64 t; cvta.to.shared.u64 t, %1; cvt.u32.u64 %0, t; }" : "=r"(a) : "l"(p));
    return a;
}
__device__ __forceinline__ void cpasync16(u32 dst, const void* src) {
    asm volatile("cp.async.ca.shared.global [%0], [%1], 16;" :: "r"(dst), "l"(src));
}
__device__ __forceinline__ void cpasync_wait() {
    asm volatile("cp.async.commit_group;\n\tcp.async.wait_group 0;" ::: "memory");
}

// ---------------- scratch globals ----------------
__device__ __align__(8) __half g_xA[BATCH * CIN * XP_CH];    // padded x fp16
__device__ __align__(8) __half g_xB[BATCH * CIN * XP_CH];    // shifted: xB[i]=xA[i+1]
__device__ __align__(8) __half g_yA[BATCH * CMID * YP_CH];   // padded y fp16
__device__ __align__(8) __half g_yB[BATCH * CMID * YP_CH];   // shifted
__device__ __align__(128) __half g_w1[4 * 8 * 128 * 128];    // [par][kc][o][krow]
__device__ __align__(128) __half g_w2[9 * 128 * 128];        // [ij][o][c]

// smem: A [128][136] halves, B [128][72] halves
#define SA2 136
#define SB 72
#define OFF_A 0
#define OFF_B 34816
#define KS32 16384                       // pac phase A: fp32 [9][64] (inside A region)
#define OFF_KSH 53248                    // pac: half2 [9][32]
#define CONVT_SMEM 53248
#define PAC_SMEM   54400

// ---------------------------------------------------------------------------
// Prep kernels
// ---------------------------------------------------------------------------
__global__ void prep_w1(const float* __restrict__ w1) {
    int idx = blockIdx.x * 256 + threadIdx.x;        // 524288
    if (idx >= 4 * 8 * 128 * 128) return;
    int kr = idx & 127;
    int o  = (idx >> 7) & 127;
    int kc = (idx >> 14) & 7;
    int par = idx >> 17;
    int di = par >> 1, dj = par & 1;
    int c = kc * 32 + (kr >> 2);
    int tap = kr & 3;
    int t = tap >> 1, u = tap & 1;
    g_w1[idx] = __float2half_rn(w1[(c * CMID + o) * 16 + (3 - di - 2 * t) * 4 + (3 - dj - 2 * u)]);
}

__global__ void prep_w2(const float* __restrict__ w2) {
    int idx = blockIdx.x * 256 + threadIdx.x;        // 147456
    if (idx >= 9 * 128 * 128) return;
    int c  = idx & 127;
    int o  = (idx >> 7) & 127;
    int ij = idx >> 14;
    int i = ij / 3, j = ij % 3;
    g_w2[idx] = __float2half_rn(w2[(c * CMID + o) * 9 + (2 - i) * 3 + (2 - j)]);
}

__global__ void pad_xk(const float* __restrict__ x) {
    int idx = blockIdx.x * 256 + threadIdx.x;        // 4595712
    if (idx >= BATCH * CIN * XP_CH) return;
    int col = idx % XP_W;
    int r   = (idx / XP_W) % XP_H;
    int bc  = idx / XP_CH;
    int h = r - 1;
    int wA = col - 1;
    int wB = col;                                    // xB[i] = xA[i+1]
    bool okh = (unsigned)h < (unsigned)H1;
    float vA = (okh && (unsigned)wA < (unsigned)W1) ? x[bc * (H1 * W1) + h * W1 + wA] : 0.f;
    float vB = (okh && (unsigned)wB < (unsigned)W1) ? x[bc * (H1 * W1) + h * W1 + wB] : 0.f;
    g_xA[idx] = __float2half_rn(vA);
    g_xB[idx] = __float2half_rn(vB);
}

__global__ void zero_y() {
    int idx = blockIdx.x * 256 + threadIdx.x;        // 2196480 u64 words
    if (idx >= (BATCH * CMID * YP_CH) / 4) return;
    ((u64*)g_yA)[idx] = 0ull;
    ((u64*)g_yB)[idx] = 0ull;
}

// ---------------------------------------------------------------------------
// MMA stage: A[128][128], B[128][64], 8 k-steps.
// ---------------------------------------------------------------------------
template<typename AccT>
__device__ __forceinline__ void mma_stage(const char* smem, int mo, int np, AccT (&acc)[2][2]) {
#pragma unroll
    for (int k0 = 0; k0 < 8; k0++) {
        const __half* B = (const __half*)(smem + OFF_B);
        const __half* A = (const __half*)(smem + OFF_A);
        wmma::fragment<wmma::matrix_b, 16, 16, 16, __half, wmma::row_major> bf[2];
        wmma::fragment<wmma::matrix_a, 16, 16, 16, __half, wmma::row_major> af[2];
        wmma::load_matrix_sync(bf[0], B + (k0 * 16) * SB + np, SB);
        wmma::load_matrix_sync(bf[1], B + (k0 * 16) * SB + np + 16, SB);
        wmma::load_matrix_sync(af[0], A + mo * SA2 + k0 * 16, SA2);
        wmma::load_matrix_sync(af[1], A + (mo + 16) * SA2 + k0 * 16, SA2);
#pragma unroll
        for (int m = 0; m < 2; m++)
#pragma unroll
            for (int n = 0; n < 2; n++)
                wmma::mma_sync(acc[m][n], af[m], bf[n], acc[m][n]);
    }
}

// ---------------------------------------------------------------------------
// Kernel 1: conv_transpose (parity decomposition). Block: 128o x 64px.
// K = 1024 in 8 chunks of 128 (32c x 4taps). B staging = aligned u32 copies.
// ---------------------------------------------------------------------------
__global__ __launch_bounds__(256, 4) void convt_wmma(const float* __restrict__ b1) {
    extern __shared__ __align__(128) char smem[];
    const u32 sb = smem_u32(smem);
    const int tid = threadIdx.x;
    const int wid = tid >> 5;
    const int mo = (wid & 3) * 32;
    const int np = (wid >> 2) * 32;

    const int bz = blockIdx.z;
    const int b  = bz >> 2;
    const int par = bz & 3;
    const int di = par >> 1, dj = par & 1;
    const int i0 = blockIdx.y * 8;
    const int j0 = blockIdx.x * 8;

    // per-thread staging coords (q-invariant); krow = wid + 8q
    const int px0 = (tid & 31) * 2;
    const int r = px0 >> 3, cw = px0 & 7;
    const int tap = wid & 3;
    const int t = tap >> 1, u = tap & 1;

    const int colc = j0 + dj + cw + u;               // padded col
    const int cpar = colc & 1;
    const __half* xsrc = cpar ? g_xB : g_xA;
    const u32* xw = (const u32*)(xsrc + ((u64)(b * CIN + (wid >> 2)) * XP_CH)
                                 + (i0 + di + r + t) * XP_W + (colc - cpar));
    char* bsm = smem + OFF_B + wid * (SB * 2) + px0 * 2;

    wmma::fragment<wmma::accumulator, 16, 16, 16, float> acc[2][2];
#pragma unroll
    for (int m = 0; m < 2; m++)
#pragma unroll
        for (int n = 0; n < 2; n++) wmma::fill_fragment(acc[m][n], 0.f);

    for (int kc = 0; kc < 8; kc++) {
        __syncthreads();
        // A: cp.async weights, 128 rows x 256B
        {
            const __half* wA = g_w1 + (par * 8 + kc) * 16384;
#pragma unroll
            for (int q = 0; q < 8; q++) {
                int p = tid + q * 256;
                int o = p >> 4, ch = p & 15;
                cpasync16(sb + OFF_A + (u32)(o * (SA2 * 2) + ch * 16), wA + o * 128 + ch * 8);
            }
        }
        // B: aligned u32 fp16 copy (channel stride per q = 2 ch = XP_CH words)
        const u32* xs = xw + kc * (16 * XP_CH);
#pragma unroll
        for (int q = 0; q < 16; q++) {
            *(u32*)(bsm + q * (8 * SB * 2)) = xs[0];
            xs += XP_CH;
        }
        cpasync_wait();
        __syncthreads();

        mma_stage(smem, mo, np, acc);
    }

    // epilogue: fbuf [128][72] fp32, parity scatter into fp16 y copies
    __syncthreads();
    float* fbuf = (float*)smem;
#pragma unroll
    for (int m = 0; m < 2; m++)
#pragma unroll
        for (int n = 0; n < 2; n++)
            wmma::store_matrix_sync(fbuf + (mo + m * 16) * SB + np + n * 16,
                                    acc[m][n], SB, wmma::mem_row_major);
    __syncthreads();
    for (int idx = tid; idx < 8192; idx += 256) {
        int o = idx >> 6;
        int n = idx & 63;
        int rr = n >> 3, cc = n & 7;
        float v = fbuf[o * SB + n] + __ldg(&b1[o]);
        __half hv = __float2half_rn(v);
        u64 base = (u64)(b * CMID + o) * YP_CH
                 + (2 * (i0 + rr) + di + 1) * YP_W + 2 * (j0 + cc) + dj + 1;
        g_yA[base] = hv;
        g_yB[base - 1] = hv;
    }
}

// ---------------------------------------------------------------------------
// Kernel 2: PAC 3x3. Block: 128o x 64px (8x8 tile). 9 ij stages, K=128 each.
// B staging = aligned u32 fp16 load + HMUL2 with pre-packed half2 k.
// ---------------------------------------------------------------------------
__global__ __launch_bounds__(256, 4) void pac_wmma(const float* __restrict__ guide,
                                                   const float* __restrict__ b2,
                                                   float* __restrict__ out) {
    extern __shared__ __align__(128) char smem[];
    const u32 sb = smem_u32(smem);
    const int tid = threadIdx.x;
    const int wid = tid >> 5;
    const int mo = (wid & 3) * 32;
    const int np = (wid >> 2) * 32;

    const int b  = blockIdx.z;
    const int h0 = blockIdx.y * 8;
    const int w0 = blockIdx.x * 8;

    float* ks32 = (float*)(smem + KS32);    // [9][64] fp32 (phase A scratch)
    u32*   ksh  = (u32*)(smem + OFF_KSH);   // [9][32] half2
    float* gs   = (float*)smem;             // overlay: [32][10][12]

    // ---- Phase A: guide kernel ----
    for (int tt = tid; tt < 576; tt += 256) ks32[tt] = 0.f;

    for (int cc = 0; cc < CMID; cc += 32) {
        __syncthreads();
        for (int idx = tid; idx < 3200; idx += 256) {
            int c = idx / 100;
            int rr = (idx % 100) / 10;
            int col = idx % 10;
            int gh = h0 - 1 + rr, gw = w0 - 1 + col;
            float v = 0.f;
            if ((unsigned)gh < (unsigned)H2 && (unsigned)gw < (unsigned)W2)
                v = guide[((b * CMID + cc + c) * H2 + gh) * W2 + gw];
            gs[c * 120 + rr * 12 + col] = v;
        }
        __syncthreads();
        for (int idx = tid; idx < 576; idx += 256) {
            int ij = idx >> 6;
            int p  = idx & 63;
            int i = ij / 3, j = ij % 3;
            int rr = p >> 3, cww = p & 7;
            float s = 0.f;
#pragma unroll
            for (int c = 0; c < 32; c++) {
                float d = gs[c * 120 + (rr + i) * 12 + (cww + j)] - gs[c * 120 + (rr + 1) * 12 + (cww + 1)];
                s += d * d;
            }
            ks32[idx] += s;
        }
    }
    __syncthreads();
    for (int tt = tid; tt < 576; tt += 256) ks32[tt] = __expf(-0.5f * ks32[tt]);
    __syncthreads();
    // pack k into half2 (outside the A/B staging regions)
    for (int tt = tid; tt < 288; tt += 256) {
        int ij = tt >> 5, p = tt & 31;
        __half2 hk = __floats2half2_rn(ks32[ij * 64 + 2 * p], ks32[ij * 64 + 2 * p + 1]);
        ksh[tt] = *(u32*)&hk;
    }
    __syncthreads();

    // ---- Phase B: 9 ij stages ----
    const int px0 = (tid & 31) * 2;
    const int r = px0 >> 3, cw = px0 & 7;
    const __half* yAb = g_yA + (u64)(b * CMID + wid) * YP_CH;
    const __half* yBb = g_yB + (u64)(b * CMID + wid) * YP_CH;
    char* bsm = smem + OFF_B + wid * (SB * 2) + px0 * 2;

    wmma::fragment<wmma::accumulator, 16, 16, 16, float> acc[2][2];
#pragma unroll
    for (int m = 0; m < 2; m++)
#pragma unroll
        for (int n = 0; n < 2; n++) wmma::fill_fragment(acc[m][n], 0.f);

    for (int ij = 0; ij < 9; ij++) {
        const int i = ij / 3, j = ij % 3;
        __syncthreads();
        // A: cp.async weights
        {
            const __half* wA = g_w2 + ij * 16384;
#pragma unroll
            for (int q = 0; q < 8; q++) {
                int p = tid + q * 256;
                int o = p >> 4, ch = p & 15;
                cpasync16(sb + OFF_A + (u32)(o * (SA2 * 2) + ch * 16), wA + o * 128 + ch * 8);
            }
        }
        // B = y * k: aligned u32 fp16 load + HMUL2 (channel stride per q = 8 ch)
        const u32 kk = ksh[ij * 32 + (tid & 31)];
        const __half2 hk = *(const __half2*)&kk;
        const __half* ysrc = (j & 1) ? yBb : yAb;
        const u32* yw = (const u32*)(ysrc + (h0 + r + i) * YP_W + w0 + cw + ((j >> 1) << 1));
#pragma unroll
        for (int q = 0; q < 16; q++) {
            __half2 v = __hmul2(*(const __half2*)yw, hk);
            *(u32*)(bsm + q * (8 * SB * 2)) = *(u32*)&v;
            yw += 4 * YP_CH;              // 8 channels = 8*YP_CH halves
        }
        cpasync_wait();
        __syncthreads();

        mma_stage(smem, mo, np, acc);
    }

    // ---- Epilogue ----
    __syncthreads();
    float* fbuf = (float*)smem;              // [128][72]
#pragma unroll
    for (int m = 0; m < 2; m++)
#pragma unroll
        for (int n = 0; n < 2; n++)
            wmma::store_matrix_sync(fbuf + (mo + m * 16) * SB + np + n * 16,
                                    acc[m][n], SB, wmma::mem_row_major);
    __syncthreads();
    for (int idx = tid; idx < 8192; idx += 256) {
        int o = idx >> 6;
        int n = idx & 63;
        float v = fbuf[o * SB + n] + __ldg(&b2[o]);
        out[((b * CMID + o) * H2 + h0 + (n >> 3)) * W2 + w0 + (n & 7)] = v;
    }
}

extern "C" void kernel_launch(void* const* d_in, const int* in_sizes, int n_in,
                              void* d_out, int out_size) {
    const float* x     = (const float*)d_in[0];
    const float* guide = (const float*)d_in[1];
    const float* w1    = (const float*)d_in[2];
    const float* b1    = (const float*)d_in[3];
    const float* w2    = (const float*)d_in[4];
    const float* b2    = (const float*)d_in[5];
    float* out = (float*)d_out;

    cudaFuncSetAttribute(convt_wmma, cudaFuncAttributeMaxDynamicSharedMemorySize, CONVT_SMEM);
    cudaFuncSetAttribute(pac_wmma, cudaFuncAttributeMaxDynamicSharedMemorySize, PAC_SMEM);

    prep_w1<<<(4 * 8 * 128 * 128 + 255) / 256, 256>>>(w1);
    prep_w2<<<(9 * 128 * 128 + 255) / 256, 256>>>(w2);
    pad_xk<<<(BATCH * CIN * XP_CH + 255) / 256, 256>>>(x);
    zero_y<<<((BATCH * CMID * YP_CH) / 4 + 255) / 256, 256>>>();
    convt_wmma<<<dim3(8, 8, BATCH * 4), 256, CONVT_SMEM>>>(b1);
    pac_wmma<<<dim3(16, 16, BATCH), 256, PAC_SMEM>>>(guide, b2, out);
}